// round 14
// baseline (speedup 1.0000x reference)
#include <cuda_runtime.h>
#include <cstdint>

#define B_ 8
#define S_ 2048
#define D_ 1024
#define DS_ 128
#define MROWS (B_*S_)   // 16384

// ---------------- scratch (static device globals; no allocation) -------------
__device__ float g_k[MROWS*DS_];
__device__ float g_v[MROWS*DS_];
__device__ float g_q[MROWS*DS_];
__device__ float g_a[MROWS*DS_];
__device__ float g_w[MROWS*DS_];    // w_t  = a_t * c0_{t-1}
__device__ float g_aq[MROWS*DS_];   // aq_t = a_t * q_t
__device__ float4 g_scal[MROWS];    // (P1, K1, E1, E0) per (b,t)
__device__ float g_y[MROWS*DS_];

// ---------------- packed fp32x2 helpers (FFMA2 path) -------------------------
typedef unsigned long long u64;

__device__ __forceinline__ u64 pk2(float lo, float hi) {
    u64 r; asm("mov.b64 %0,{%1,%2};" : "=l"(r) : "f"(lo), "f"(hi)); return r;
}
__device__ __forceinline__ float2 up2(u64 v) {
    float2 r; asm("mov.b64 {%0,%1}, %2;" : "=f"(r.x), "=f"(r.y) : "l"(v)); return r;
}
__device__ __forceinline__ u64 ffma2(u64 a, u64 b, u64 c) {
    u64 d; asm("fma.rn.f32x2 %0,%1,%2,%3;" : "=l"(d) : "l"(a), "l"(b), "l"(c)); return d;
}
__device__ __forceinline__ u64 fmul2(u64 a, u64 b) {
    u64 d; asm("mul.rn.f32x2 %0,%1,%2;" : "=l"(d) : "l"(a), "l"(b)); return d;
}
__device__ __forceinline__ u64 fadd2(u64 a, u64 b) {
    u64 d; asm("add.rn.f32x2 %0,%1,%2;" : "=l"(d) : "l"(a), "l"(b)); return d;
}

// =============================================================================
// Kernel 1: input projections. O = X @ W^T with per-variant epilogue.
// =============================================================================
__global__ __launch_bounds__(256) void proj_kernel(
    const float* __restrict__ x,
    const float* __restrict__ Wk, const float* __restrict__ Wv,
    const float* __restrict__ Wq, const float* __restrict__ Waw,
    const float* __restrict__ Wab, const float* __restrict__ lam)
{
    const int which = blockIdx.y;
    const float* W; float* O; int epi;
    if (which == 0)      { W = Wk;  O = g_k; epi = 1; }
    else if (which == 1) { W = Wq;  O = g_q; epi = 1; }
    else if (which == 2) { W = Wv;  O = g_v; epi = 0; }
    else                 { W = Waw; O = g_a; epi = 2; }

    __shared__ __align__(16) float sX[16][68];
    __shared__ __align__(16) float sW[16][132];

    const int tid = threadIdx.x;
    const int tx  = tid & 31;
    const int ty  = tid >> 5;
    const int m0  = blockIdx.x * 64;

    u64 acc2[8][2];
#pragma unroll
    for (int i = 0; i < 8; i++) { acc2[i][0] = 0ULL; acc2[i][1] = 0ULL; }

    const int lxr = tid >> 2;
    const int lxk = (tid & 3) * 4;

    for (int kc = 0; kc < D_; kc += 16) {
        float4 xv = *(const float4*)&x[(size_t)(m0 + lxr) * D_ + kc + lxk];
        int n0a = tid >> 2, k0a = (tid & 3) * 4;
        float4 wv0 = *(const float4*)&W[(size_t)n0a * D_ + kc + k0a];
        int idx2 = tid + 256;
        int n0b = idx2 >> 2, k0b = (idx2 & 3) * 4;
        float4 wv1 = *(const float4*)&W[(size_t)n0b * D_ + kc + k0b];

        __syncthreads();
        sX[lxk + 0][lxr] = xv.x; sX[lxk + 1][lxr] = xv.y;
        sX[lxk + 2][lxr] = xv.z; sX[lxk + 3][lxr] = xv.w;
        sW[k0a + 0][n0a] = wv0.x; sW[k0a + 1][n0a] = wv0.y;
        sW[k0a + 2][n0a] = wv0.z; sW[k0a + 3][n0a] = wv0.w;
        sW[k0b + 0][n0b] = wv1.x; sW[k0b + 1][n0b] = wv1.y;
        sW[k0b + 2][n0b] = wv1.z; sW[k0b + 3][n0b] = wv1.w;
        __syncthreads();

#pragma unroll
        for (int k = 0; k < 16; k++) {
            ulonglong2 b4 = *(const ulonglong2*)&sW[k][tx * 4];
            float a_[8];
#pragma unroll
            for (int i = 0; i < 8; i++) a_[i] = sX[k][ty * 8 + i];
#pragma unroll
            for (int i = 0; i < 8; i++) {
                u64 a2 = pk2(a_[i], a_[i]);
                acc2[i][0] = ffma2(a2, b4.x, acc2[i][0]);
                acc2[i][1] = ffma2(a2, b4.y, acc2[i][1]);
            }
        }
    }

    float acc[8][4];
#pragma unroll
    for (int i = 0; i < 8; i++) {
        float2 lo = up2(acc2[i][0]);
        float2 hi = up2(acc2[i][1]);
        acc[i][0] = lo.x; acc[i][1] = lo.y; acc[i][2] = hi.x; acc[i][3] = hi.y;
    }

    const int nbase = tx * 4;
    if (epi == 0) {
#pragma unroll
        for (int i = 0; i < 8; i++) {
            float4 o = make_float4(acc[i][0], acc[i][1], acc[i][2], acc[i][3]);
            *(float4*)&O[(size_t)(m0 + ty * 8 + i) * DS_ + nbase] = o;
        }
    } else if (epi == 1) {
#pragma unroll
        for (int i = 0; i < 8; i++) {
            float ss = acc[i][0] * acc[i][0] + acc[i][1] * acc[i][1]
                     + acc[i][2] * acc[i][2] + acc[i][3] * acc[i][3];
#pragma unroll
            for (int off = 16; off; off >>= 1)
                ss += __shfl_xor_sync(0xffffffffu, ss, off);
            float inv = 1.f / fmaxf(sqrtf(ss), 1e-12f);
            float4 o = make_float4(acc[i][0] * inv, acc[i][1] * inv,
                                   acc[i][2] * inv, acc[i][3] * inv);
            *(float4*)&O[(size_t)(m0 + ty * 8 + i) * DS_ + nbase] = o;
        }
    } else {
        float bias[4], loga[4];
#pragma unroll
        for (int j = 0; j < 4; j++) {
            int n = nbase + j;
            bias[j] = Wab[n];
            float sl = 1.f / (1.f + __expf(-lam[n]));
            loga[j] = __logf(sl + 1e-8f);
        }
#pragma unroll
        for (int i = 0; i < 8; i++) {
            float4 o;
            float r0 = 1.f / (1.f + __expf(-(acc[i][0] + bias[0])));
            float r1 = 1.f / (1.f + __expf(-(acc[i][1] + bias[1])));
            float r2 = 1.f / (1.f + __expf(-(acc[i][2] + bias[2])));
            float r3 = 1.f / (1.f + __expf(-(acc[i][3] + bias[3])));
            o.x = __expf(8.f * r0 * loga[0]);
            o.y = __expf(8.f * r1 * loga[1]);
            o.z = __expf(8.f * r2 * loga[2]);
            o.w = __expf(8.f * r3 * loga[3]);
            *(float4*)&O[(size_t)(m0 + ty * 8 + i) * DS_ + nbase] = o;
        }
    }
}

// =============================================================================
// Kernel 1b: derive per-step vectors and scalars (parallel over (b,t)).
// =============================================================================
__global__ __launch_bounds__(256) void derive_kernel()
{
    const int m = (blockIdx.x * 256 + threadIdx.x) >> 5;   // global row
    const int lane = threadIdx.x & 31;
    if (m >= MROWS) return;
    const int t = m & (S_ - 1);
    const size_t ro = (size_t)m * DS_ + lane * 4;

    float4 qt = *(const float4*)&g_q[ro];
    float4 kt = *(const float4*)&g_k[ro];
    float4 at = *(const float4*)&g_a[ro];
    float4 kp = make_float4(0.f, 0.f, 0.f, 0.f);
    float4 ap = make_float4(1.f, 1.f, 1.f, 1.f);   // (1-ap)=0 -> c0p = 0 at t=0
    if (t > 0) {
        kp = *(const float4*)&g_k[ro - DS_];
        ap = *(const float4*)&g_a[ro - DS_];
    }

    float4 c0p, w, aq, c0c;
    c0p.x = (1.f - ap.x) * kp.x; c0p.y = (1.f - ap.y) * kp.y;
    c0p.z = (1.f - ap.z) * kp.z; c0p.w = (1.f - ap.w) * kp.w;
    w.x = at.x * c0p.x; w.y = at.y * c0p.y; w.z = at.z * c0p.z; w.w = at.w * c0p.w;
    aq.x = at.x * qt.x; aq.y = at.y * qt.y; aq.z = at.z * qt.z; aq.w = at.w * qt.w;
    c0c.x = (1.f - at.x) * kt.x; c0c.y = (1.f - at.y) * kt.y;
    c0c.z = (1.f - at.z) * kt.z; c0c.w = (1.f - at.w) * kt.w;

    float P1 = qt.x * c0p.x + qt.y * c0p.y + qt.z * c0p.z + qt.w * c0p.w;
    float K1 = kt.x * c0p.x + kt.y * c0p.y + kt.z * c0p.z + kt.w * c0p.w;
    float E1 = qt.x * w.x + qt.y * w.y + qt.z * w.z + qt.w * w.w;
    float E0 = qt.x * c0c.x + qt.y * c0c.y + qt.z * c0c.z + qt.w * c0c.w;
#pragma unroll
    for (int off = 16; off; off >>= 1) {
        P1 += __shfl_xor_sync(0xffffffffu, P1, off);
        K1 += __shfl_xor_sync(0xffffffffu, K1, off);
        E1 += __shfl_xor_sync(0xffffffffu, E1, off);
        E0 += __shfl_xor_sync(0xffffffffu, E0, off);
    }

    *(float4*)&g_w[ro]  = w;
    *(float4*)&g_aq[ro] = aq;
    if (lane == 0) g_scal[m] = make_float4(P1, K1, E1, E0);
}

// =============================================================================
// Kernel 2: recurrence, deferred rank-1. 128 threads/CTA, 1 CTA per batch
// (the measured-best regime). Fused single pass over g per step (matvec with
// old g, then in-place update with sdv_{t-1}); t-loop unrolled by 2 so step
// t's post-barrier scalar tail overlaps step t+1's independent matvec stream
// in one straight-line scheduling region. One barrier per step.
// =============================================================================
__global__ __launch_bounds__(128, 1) void recurrence_kernel()
{
    const int b    = blockIdx.x;
    const int c    = threadIdx.x;
    const int warp = c >> 5;
    const int lane = c & 31;

    __shared__ __align__(16) float sq[2][DS_];
    __shared__ __align__(16) float sk[2][DS_];
    __shared__ __align__(16) float saq[2][DS_];
    __shared__ __align__(16) float sa[2][DS_];
    __shared__ __align__(16) float sw[2][DS_];
    __shared__ __align__(16) float sv2[2][DS_];
    __shared__ float4 ssc[2];
    __shared__ __align__(16) float red[2][4];

    u64 g[64];
#pragma unroll
    for (int j = 0; j < 64; j++) g[j] = 0ULL;

    const size_t base = (size_t)b * S_ * DS_;
    const float* bq  = g_q  + base;
    const float* bk  = g_k  + base;
    const float* baq = g_aq + base;
    const float* ba  = g_a  + base;
    const float* bw  = g_w  + base;
    const float* bv  = g_v  + base;
    const float4* bs = g_scal + (size_t)b * S_;
    float* by = g_y + base;

    // preload step 0 into buffer 0
    sq[0][c] = bq[c];  sk[0][c] = bk[c]; saq[0][c] = baq[c];
    sa[0][c] = ba[c];  sw[0][c] = bw[c]; sv2[0][c] = bv[c];
    if (c == 0) ssc[0] = bs[0];
    __syncthreads();

    float sdvprev = 0.f;

    // one recurrence step with static buffer indices (BUF in use, NB stash)
#define REC_STEP(BUF, NB, TCUR)                                                \
    {                                                                          \
        const int tcur = (TCUR);                                               \
        float f0 = 0.f, f1 = 0.f, f2 = 0.f, f3 = 0.f, f4 = 0.f, f5 = 0.f;      \
        float4 sc4 = make_float4(0.f, 0.f, 0.f, 0.f);                          \
        if (tcur + 1 < S_) {                                                   \
            size_t o = (size_t)(tcur + 1) * DS_ + c;                           \
            f0 = bq[o]; f1 = bk[o]; f2 = baq[o];                               \
            f3 = ba[o]; f4 = bw[o]; f5 = bv[o];                                \
            if (c == 0) sc4 = bs[tcur + 1];                                    \
        }                                                                      \
        const ulonglong2* Q  = (const ulonglong2*)&sq[BUF][0];                 \
        const ulonglong2* K  = (const ulonglong2*)&sk[BUF][0];                 \
        const ulonglong2* AQ = (const ulonglong2*)&saq[BUF][0];                \
        const ulonglong2* A  = (const ulonglong2*)&sa[BUF][0];                 \
        const ulonglong2* Wp = (const ulonglong2*)&sw[BUF][0];                 \
        u64 mq0 = 0, mq1 = 0, mk0 = 0, mk1 = 0, ma0 = 0, ma1 = 0;              \
        u64 sp2 = pk2(sdvprev, sdvprev);                                       \
        _Pragma("unroll")                                                      \
        for (int j = 0; j < 32; j++) {                                         \
            ulonglong2 q2 = Q[j];                                              \
            ulonglong2 k2 = K[j];                                              \
            ulonglong2 a2 = AQ[j];                                             \
            ulonglong2 aa = A[j];                                              \
            ulonglong2 ww = Wp[j];                                             \
            u64 g0 = g[2 * j], g1 = g[2 * j + 1];                              \
            mq0 = ffma2(q2.x, g0, mq0);                                        \
            mk0 = ffma2(k2.x, g0, mk0);                                        \
            ma0 = ffma2(a2.x, g0, ma0);                                        \
            mq1 = ffma2(q2.y, g1, mq1);                                        \
            mk1 = ffma2(k2.y, g1, mk1);                                        \
            ma1 = ffma2(a2.y, g1, ma1);                                        \
            g[2 * j]     = ffma2(aa.x, g0, fmul2(ww.x, sp2));                  \
            g[2 * j + 1] = ffma2(aa.y, g1, fmul2(ww.y, sp2));                  \
        }                                                                      \
        float2 t1 = up2(fadd2(mq0, mq1));                                      \
        float Mq = t1.x + t1.y;                                                \
        float2 t2 = up2(fadd2(mk0, mk1));                                      \
        float Mk = t2.x + t2.y;                                                \
        float2 t3 = up2(fadd2(ma0, ma1));                                      \
        float Mqa = t3.x + t3.y;                                               \
        float4 scv = ssc[BUF];                                                 \
        float myv  = sv2[BUF][c];                                              \
        float pred = Mq + sdvprev * scv.x;                                     \
        float d = myv - pred;                                                  \
        float e = d * d;                                                       \
        _Pragma("unroll")                                                      \
        for (int off = 16; off; off >>= 1)                                     \
            e += __shfl_xor_sync(0xffffffffu, e, off);                         \
        if (lane == 0) red[BUF][warp] = e;                                     \
        if (tcur + 1 < S_) {                                                   \
            sq[NB][c] = f0;  sk[NB][c] = f1; saq[NB][c] = f2;                  \
            sa[NB][c] = f3;  sw[NB][c] = f4; sv2[NB][c] = f5;                  \
            if (c == 0) ssc[NB] = sc4;                                         \
        }                                                                      \
        __syncthreads();                                                       \
        float4 r4 = *(const float4*)&red[BUF][0];                              \
        float err = (r4.x + r4.y) + (r4.z + r4.w);                             \
        float sur = 1.f / (1.f + __expf(-err * (1.f / 1.000001f)));            \
        float kp  = Mk + sdvprev * scv.y;                                      \
        float sdv = sur * (myv - kp);                                          \
        float y = Mqa + sdvprev * scv.z + sdv * scv.w;                         \
        by[(size_t)tcur * DS_ + c] = y;                                        \
        sdvprev = sdv;                                                         \
    }

    for (int t = 0; t < S_; t += 2) {
        REC_STEP(0, 1, t)
        REC_STEP(1, 0, t + 1)
    }
#undef REC_STEP
}

// =============================================================================
// Kernel 3: fused RMSNorm(y) * norm_weight, then @ W_o^T. Packed FFMA2.
// =============================================================================
__global__ __launch_bounds__(256) void out_kernel(
    const float* __restrict__ Wo, const float* __restrict__ nw,
    float* __restrict__ out)
{
    __shared__ __align__(16) float sY[128][68];   // [k][m]
    __shared__ __align__(16) float sW[16][132];   // [k][n]
    __shared__ float sScale[64];
    __shared__ float snw[128];

    const int tid = threadIdx.x;
    const int tx = tid & 31, ty = tid >> 5;
    const int m0 = blockIdx.x * 64, n0 = blockIdx.y * 128;

    if (tid < 128) snw[tid] = nw[tid];

#pragma unroll
    for (int it = 0; it < 8; it++) {
        int idx = tid + it * 256;
        int row = idx >> 5;
        int k4  = (idx & 31) * 4;
        float4 v = *(const float4*)&g_y[(size_t)(m0 + row) * DS_ + k4];
        sY[k4 + 0][row] = v.x; sY[k4 + 1][row] = v.y;
        sY[k4 + 2][row] = v.z; sY[k4 + 3][row] = v.w;
    }
    __syncthreads();

    {
        int row = tid >> 2, part = tid & 3;
        float ss = 0.f;
#pragma unroll
        for (int kkk = 0; kkk < 32; kkk++) {
            float v = sY[part * 32 + kkk][row];
            ss = fmaf(v, v, ss);
        }
        ss += __shfl_xor_sync(0xffffffffu, ss, 1);
        ss += __shfl_xor_sync(0xffffffffu, ss, 2);
        if (part == 0) sScale[row] = rsqrtf(ss * (1.f / 128.f) + 1e-6f);
    }
    __syncthreads();

    for (int idx = tid; idx < 128 * 64; idx += 256) {
        int k = idx >> 6, m = idx & 63;
        sY[k][m] *= sScale[m];
    }

    u64 acc2[8][2];
#pragma unroll
    for (int i = 0; i < 8; i++) { acc2[i][0] = 0ULL; acc2[i][1] = 0ULL; }

    for (int kc = 0; kc < DS_; kc += 16) {
        int n0a = tid >> 2, k0a = (tid & 3) * 4;
        float4 w0 = *(const float4*)&Wo[(size_t)(n0 + n0a) * DS_ + kc + k0a];
        int idx2 = tid + 256;
        int n0b = idx2 >> 2, k0b = (idx2 & 3) * 4;
        float4 w1 = *(const float4*)&Wo[(size_t)(n0 + n0b) * DS_ + kc + k0b];

        __syncthreads();
        sW[k0a + 0][n0a] = w0.x * snw[kc + k0a + 0];
        sW[k0a + 1][n0a] = w0.y * snw[kc + k0a + 1];
        sW[k0a + 2][n0a] = w0.z * snw[kc + k0a + 2];
        sW[k0a + 3][n0a] = w0.w * snw[kc + k0a + 3];
        sW[k0b + 0][n0b] = w1.x * snw[kc + k0b + 0];
        sW[k0b + 1][n0b] = w1.y * snw[kc + k0b + 1];
        sW[k0b + 2][n0b] = w1.z * snw[kc + k0b + 2];
        sW[k0b + 3][n0b] = w1.w * snw[kc + k0b + 3];
        __syncthreads();

#pragma unroll
        for (int k = 0; k < 16; k++) {
            ulonglong2 b4 = *(const ulonglong2*)&sW[k][tx * 4];
            float a_[8];
#pragma unroll
            for (int i = 0; i < 8; i++) a_[i] = sY[kc + k][ty * 8 + i];
#pragma unroll
            for (int i = 0; i < 8; i++) {
                u64 a2 = pk2(a_[i], a_[i]);
                acc2[i][0] = ffma2(a2, b4.x, acc2[i][0]);
                acc2[i][1] = ffma2(a2, b4.y, acc2[i][1]);
            }
        }
    }

#pragma unroll
    for (int i = 0; i < 8; i++) {
        float2 lo = up2(acc2[i][0]);
        float2 hi = up2(acc2[i][1]);
        float4 o = make_float4(lo.x, lo.y, hi.x, hi.y);
        *(float4*)&out[(size_t)(m0 + ty * 8 + i) * D_ + n0 + tx * 4] = o;
    }
}

// =============================================================================
extern "C" void kernel_launch(void* const* d_in, const int* in_sizes, int n_in,
                              void* d_out, int out_size)
{
    const float* x   = (const float*)d_in[0];
    const float* Wk  = (const float*)d_in[1];
    const float* Wv  = (const float*)d_in[2];
    const float* Wq  = (const float*)d_in[3];
    const float* Waw = (const float*)d_in[4];
    const float* Wab = (const float*)d_in[5];
    const float* lam = (const float*)d_in[6];
    const float* Wo  = (const float*)d_in[7];
    const float* nw  = (const float*)d_in[8];
    float* out = (float*)d_out;

    dim3 g1(MROWS / 64, 4);
    proj_kernel<<<g1, 256>>>(x, Wk, Wv, Wq, Waw, Wab, lam);

    derive_kernel<<<MROWS / 8, 256>>>();

    recurrence_kernel<<<B_, 128>>>();

    dim3 g3(MROWS / 64, D_ / 128);
    out_kernel<<<g3, 256>>>(Wo, nw, out);
}

// round 15
// speedup vs baseline: 1.5425x; 1.5425x over previous
#include <cuda_runtime.h>
#include <cstdint>

#define B_ 8
#define S_ 2048
#define D_ 1024
#define DS_ 128
#define MROWS (B_*S_)   // 16384

// ---------------- scratch (static device globals; no allocation) -------------
__device__ float g_k[MROWS*DS_];
__device__ float g_v[MROWS*DS_];
__device__ float g_q[MROWS*DS_];
__device__ float g_a[MROWS*DS_];
__device__ float g_w[MROWS*DS_];    // w_t  = a_t * c0_{t-1}
__device__ float g_aq[MROWS*DS_];   // aq_t = a_t * q_t
__device__ float4 g_scal[MROWS];    // (P1, K1, E1, E0) per (b,t)
__device__ float g_y[MROWS*DS_];

// ---------------- packed fp32x2 helpers (FFMA2 path) -------------------------
typedef unsigned long long u64;

__device__ __forceinline__ u64 pk2(float lo, float hi) {
    u64 r; asm("mov.b64 %0,{%1,%2};" : "=l"(r) : "f"(lo), "f"(hi)); return r;
}
__device__ __forceinline__ float2 up2(u64 v) {
    float2 r; asm("mov.b64 {%0,%1}, %2;" : "=f"(r.x), "=f"(r.y) : "l"(v)); return r;
}
__device__ __forceinline__ u64 ffma2(u64 a, u64 b, u64 c) {
    u64 d; asm("fma.rn.f32x2 %0,%1,%2,%3;" : "=l"(d) : "l"(a), "l"(b), "l"(c)); return d;
}
__device__ __forceinline__ u64 fmul2(u64 a, u64 b) {
    u64 d; asm("mul.rn.f32x2 %0,%1,%2;" : "=l"(d) : "l"(a), "l"(b)); return d;
}
__device__ __forceinline__ u64 fadd2(u64 a, u64 b) {
    u64 d; asm("add.rn.f32x2 %0,%1,%2;" : "=l"(d) : "l"(a), "l"(b)); return d;
}

// =============================================================================
// Kernel 1: input projections. O = X @ W^T with per-variant epilogue.
// =============================================================================
__global__ __launch_bounds__(256) void proj_kernel(
    const float* __restrict__ x,
    const float* __restrict__ Wk, const float* __restrict__ Wv,
    const float* __restrict__ Wq, const float* __restrict__ Waw,
    const float* __restrict__ Wab, const float* __restrict__ lam)
{
    const int which = blockIdx.y;
    const float* W; float* O; int epi;
    if (which == 0)      { W = Wk;  O = g_k; epi = 1; }
    else if (which == 1) { W = Wq;  O = g_q; epi = 1; }
    else if (which == 2) { W = Wv;  O = g_v; epi = 0; }
    else                 { W = Waw; O = g_a; epi = 2; }

    __shared__ __align__(16) float sX[16][68];
    __shared__ __align__(16) float sW[16][132];

    const int tid = threadIdx.x;
    const int tx  = tid & 31;
    const int ty  = tid >> 5;
    const int m0  = blockIdx.x * 64;

    u64 acc2[8][2];
#pragma unroll
    for (int i = 0; i < 8; i++) { acc2[i][0] = 0ULL; acc2[i][1] = 0ULL; }

    const int lxr = tid >> 2;
    const int lxk = (tid & 3) * 4;

    for (int kc = 0; kc < D_; kc += 16) {
        float4 xv = *(const float4*)&x[(size_t)(m0 + lxr) * D_ + kc + lxk];
        int n0a = tid >> 2, k0a = (tid & 3) * 4;
        float4 wv0 = *(const float4*)&W[(size_t)n0a * D_ + kc + k0a];
        int idx2 = tid + 256;
        int n0b = idx2 >> 2, k0b = (idx2 & 3) * 4;
        float4 wv1 = *(const float4*)&W[(size_t)n0b * D_ + kc + k0b];

        __syncthreads();
        sX[lxk + 0][lxr] = xv.x; sX[lxk + 1][lxr] = xv.y;
        sX[lxk + 2][lxr] = xv.z; sX[lxk + 3][lxr] = xv.w;
        sW[k0a + 0][n0a] = wv0.x; sW[k0a + 1][n0a] = wv0.y;
        sW[k0a + 2][n0a] = wv0.z; sW[k0a + 3][n0a] = wv0.w;
        sW[k0b + 0][n0b] = wv1.x; sW[k0b + 1][n0b] = wv1.y;
        sW[k0b + 2][n0b] = wv1.z; sW[k0b + 3][n0b] = wv1.w;
        __syncthreads();

#pragma unroll
        for (int k = 0; k < 16; k++) {
            ulonglong2 b4 = *(const ulonglong2*)&sW[k][tx * 4];
            float a_[8];
#pragma unroll
            for (int i = 0; i < 8; i++) a_[i] = sX[k][ty * 8 + i];
#pragma unroll
            for (int i = 0; i < 8; i++) {
                u64 a2 = pk2(a_[i], a_[i]);
                acc2[i][0] = ffma2(a2, b4.x, acc2[i][0]);
                acc2[i][1] = ffma2(a2, b4.y, acc2[i][1]);
            }
        }
    }

    float acc[8][4];
#pragma unroll
    for (int i = 0; i < 8; i++) {
        float2 lo = up2(acc2[i][0]);
        float2 hi = up2(acc2[i][1]);
        acc[i][0] = lo.x; acc[i][1] = lo.y; acc[i][2] = hi.x; acc[i][3] = hi.y;
    }

    const int nbase = tx * 4;
    if (epi == 0) {
#pragma unroll
        for (int i = 0; i < 8; i++) {
            float4 o = make_float4(acc[i][0], acc[i][1], acc[i][2], acc[i][3]);
            *(float4*)&O[(size_t)(m0 + ty * 8 + i) * DS_ + nbase] = o;
        }
    } else if (epi == 1) {
#pragma unroll
        for (int i = 0; i < 8; i++) {
            float ss = acc[i][0] * acc[i][0] + acc[i][1] * acc[i][1]
                     + acc[i][2] * acc[i][2] + acc[i][3] * acc[i][3];
#pragma unroll
            for (int off = 16; off; off >>= 1)
                ss += __shfl_xor_sync(0xffffffffu, ss, off);
            float inv = 1.f / fmaxf(sqrtf(ss), 1e-12f);
            float4 o = make_float4(acc[i][0] * inv, acc[i][1] * inv,
                                   acc[i][2] * inv, acc[i][3] * inv);
            *(float4*)&O[(size_t)(m0 + ty * 8 + i) * DS_ + nbase] = o;
        }
    } else {
        float bias[4], loga[4];
#pragma unroll
        for (int j = 0; j < 4; j++) {
            int n = nbase + j;
            bias[j] = Wab[n];
            float sl = 1.f / (1.f + __expf(-lam[n]));
            loga[j] = __logf(sl + 1e-8f);
        }
#pragma unroll
        for (int i = 0; i < 8; i++) {
            float4 o;
            float r0 = 1.f / (1.f + __expf(-(acc[i][0] + bias[0])));
            float r1 = 1.f / (1.f + __expf(-(acc[i][1] + bias[1])));
            float r2 = 1.f / (1.f + __expf(-(acc[i][2] + bias[2])));
            float r3 = 1.f / (1.f + __expf(-(acc[i][3] + bias[3])));
            o.x = __expf(8.f * r0 * loga[0]);
            o.y = __expf(8.f * r1 * loga[1]);
            o.z = __expf(8.f * r2 * loga[2]);
            o.w = __expf(8.f * r3 * loga[3]);
            *(float4*)&O[(size_t)(m0 + ty * 8 + i) * DS_ + nbase] = o;
        }
    }
}

// =============================================================================
// Kernel 1b: derive per-step vectors and scalars (parallel over (b,t)).
// =============================================================================
__global__ __launch_bounds__(256) void derive_kernel()
{
    const int m = (blockIdx.x * 256 + threadIdx.x) >> 5;   // global row
    const int lane = threadIdx.x & 31;
    if (m >= MROWS) return;
    const int t = m & (S_ - 1);
    const size_t ro = (size_t)m * DS_ + lane * 4;

    float4 qt = *(const float4*)&g_q[ro];
    float4 kt = *(const float4*)&g_k[ro];
    float4 at = *(const float4*)&g_a[ro];
    float4 kp = make_float4(0.f, 0.f, 0.f, 0.f);
    float4 ap = make_float4(1.f, 1.f, 1.f, 1.f);   // (1-ap)=0 -> c0p = 0 at t=0
    if (t > 0) {
        kp = *(const float4*)&g_k[ro - DS_];
        ap = *(const float4*)&g_a[ro - DS_];
    }

    float4 c0p, w, aq, c0c;
    c0p.x = (1.f - ap.x) * kp.x; c0p.y = (1.f - ap.y) * kp.y;
    c0p.z = (1.f - ap.z) * kp.z; c0p.w = (1.f - ap.w) * kp.w;
    w.x = at.x * c0p.x; w.y = at.y * c0p.y; w.z = at.z * c0p.z; w.w = at.w * c0p.w;
    aq.x = at.x * qt.x; aq.y = at.y * qt.y; aq.z = at.z * qt.z; aq.w = at.w * qt.w;
    c0c.x = (1.f - at.x) * kt.x; c0c.y = (1.f - at.y) * kt.y;
    c0c.z = (1.f - at.z) * kt.z; c0c.w = (1.f - at.w) * kt.w;

    float P1 = qt.x * c0p.x + qt.y * c0p.y + qt.z * c0p.z + qt.w * c0p.w;
    float K1 = kt.x * c0p.x + kt.y * c0p.y + kt.z * c0p.z + kt.w * c0p.w;
    float E1 = qt.x * w.x + qt.y * w.y + qt.z * w.z + qt.w * w.w;
    float E0 = qt.x * c0c.x + qt.y * c0c.y + qt.z * c0c.z + qt.w * c0c.w;
#pragma unroll
    for (int off = 16; off; off >>= 1) {
        P1 += __shfl_xor_sync(0xffffffffu, P1, off);
        K1 += __shfl_xor_sync(0xffffffffu, K1, off);
        E1 += __shfl_xor_sync(0xffffffffu, E1, off);
        E0 += __shfl_xor_sync(0xffffffffu, E0, off);
    }

    *(float4*)&g_w[ro]  = w;
    *(float4*)&g_aq[ro] = aq;
    if (lane == 0) g_scal[m] = make_float4(P1, K1, E1, E0);
}

// =============================================================================
// Kernel 2: recurrence, deferred rank-1. 128 threads/CTA, 1 CTA per batch.
// EXACT R12 iteration body (separate loop A matvecs and loop B update), but
// t-loop unrolled by 2 with static buffer indices so step t's serial tail
// (LDS red -> err -> sigmoid -> sdv) sits in the same straight-line region as
// step t+1's INDEPENDENT loop A, letting the scheduler fill the tail's stalls.
// Loop B of t+1 (the only sdv_t consumer) comes late enough to be ready.
// =============================================================================
__global__ __launch_bounds__(128, 1) void recurrence_kernel()
{
    const int b    = blockIdx.x;
    const int c    = threadIdx.x;
    const int warp = c >> 5;
    const int lane = c & 31;

    __shared__ __align__(16) float sq[2][DS_];
    __shared__ __align__(16) float sk[2][DS_];
    __shared__ __align__(16) float saq[2][DS_];
    __shared__ __align__(16) float sa[2][DS_];
    __shared__ __align__(16) float sw[2][DS_];
    __shared__ __align__(16) float sv2[2][DS_];
    __shared__ float4 ssc[2];
    __shared__ __align__(16) float red[2][4];

    u64 g[64];
#pragma unroll
    for (int j = 0; j < 64; j++) g[j] = 0ULL;

    const size_t base = (size_t)b * S_ * DS_;
    const float* bq  = g_q  + base;
    const float* bk  = g_k  + base;
    const float* baq = g_aq + base;
    const float* ba  = g_a  + base;
    const float* bw  = g_w  + base;
    const float* bv  = g_v  + base;
    const float4* bs = g_scal + (size_t)b * S_;
    float* by = g_y + base;

    // preload step 0 into buffer 0
    sq[0][c] = bq[c];  sk[0][c] = bk[c]; saq[0][c] = baq[c];
    sa[0][c] = ba[c];  sw[0][c] = bw[c]; sv2[0][c] = bv[c];
    if (c == 0) ssc[0] = bs[0];
    __syncthreads();

    float sdvprev = 0.f;

    // EXACT R12 step body; only the buffer indices are compile-time constants.
#define REC_STEP(BUF, NB, TCUR)                                                \
    {                                                                          \
        const int tcur = (TCUR);                                               \
        float f0 = 0.f, f1 = 0.f, f2 = 0.f, f3 = 0.f, f4 = 0.f, f5 = 0.f;      \
        float4 sc4 = make_float4(0.f, 0.f, 0.f, 0.f);                          \
        if (tcur + 1 < S_) {                                                   \
            size_t o = (size_t)(tcur + 1) * DS_ + c;                           \
            f0 = bq[o]; f1 = bk[o]; f2 = baq[o];                               \
            f3 = ba[o]; f4 = bw[o]; f5 = bv[o];                                \
            if (c == 0) sc4 = bs[tcur + 1];                                    \
        }                                                                      \
        /* loop A: three matvecs vs g (broadcast LDS, 6 acc chains) */         \
        const ulonglong2* Q  = (const ulonglong2*)&sq[BUF][0];                 \
        const ulonglong2* K  = (const ulonglong2*)&sk[BUF][0];                 \
        const ulonglong2* AQ = (const ulonglong2*)&saq[BUF][0];                \
        u64 mq0 = 0, mq1 = 0, mk0 = 0, mk1 = 0, ma0 = 0, ma1 = 0;              \
        _Pragma("unroll")                                                      \
        for (int j = 0; j < 32; j++) {                                         \
            ulonglong2 q2 = Q[j];                                              \
            ulonglong2 k2 = K[j];                                              \
            ulonglong2 a2 = AQ[j];                                             \
            mq0 = ffma2(q2.x, g[2 * j],     mq0);                              \
            mk0 = ffma2(k2.x, g[2 * j],     mk0);                              \
            ma0 = ffma2(a2.x, g[2 * j],     ma0);                              \
            mq1 = ffma2(q2.y, g[2 * j + 1], mq1);                              \
            mk1 = ffma2(k2.y, g[2 * j + 1], mk1);                              \
            ma1 = ffma2(a2.y, g[2 * j + 1], ma1);                              \
        }                                                                      \
        float2 t1 = up2(fadd2(mq0, mq1));                                      \
        float Mq = t1.x + t1.y;                                                \
        float2 t2 = up2(fadd2(mk0, mk1));                                      \
        float Mk = t2.x + t2.y;                                                \
        float2 t3 = up2(fadd2(ma0, ma1));                                      \
        float Mqa = t3.x + t3.y;                                               \
        float4 scv = ssc[BUF];                                                 \
        float myv  = sv2[BUF][c];                                              \
        float pred = Mq + sdvprev * scv.x;                                     \
        float d = myv - pred;                                                  \
        float e = d * d;                                                       \
        _Pragma("unroll")                                                      \
        for (int off = 16; off; off >>= 1)                                     \
            e += __shfl_xor_sync(0xffffffffu, e, off);                         \
        if (lane == 0) red[BUF][warp] = e;                                     \
        /* loop B: g = a*g + sdvprev*w (independent of sur_t) */               \
        const ulonglong2* A   = (const ulonglong2*)&sa[BUF][0];                \
        const ulonglong2* Wp  = (const ulonglong2*)&sw[BUF][0];                \
        u64 sp2 = pk2(sdvprev, sdvprev);                                       \
        _Pragma("unroll")                                                      \
        for (int j = 0; j < 32; j++) {                                         \
            ulonglong2 a2 = A[j];                                              \
            ulonglong2 w2 = Wp[j];                                             \
            g[2 * j]     = ffma2(a2.x, g[2 * j],     fmul2(w2.x, sp2));        \
            g[2 * j + 1] = ffma2(a2.y, g[2 * j + 1], fmul2(w2.y, sp2));        \
        }                                                                      \
        if (tcur + 1 < S_) {                                                   \
            sq[NB][c] = f0;  sk[NB][c] = f1; saq[NB][c] = f2;                  \
            sa[NB][c] = f3;  sw[NB][c] = f4; sv2[NB][c] = f5;                  \
            if (c == 0) ssc[NB] = sc4;                                         \
        }                                                                      \
        __syncthreads();                                                       \
        float4 r4 = *(const float4*)&red[BUF][0];                              \
        float err = (r4.x + r4.y) + (r4.z + r4.w);                             \
        float sur = 1.f / (1.f + __expf(-err * (1.f / 1.000001f)));            \
        float kp  = Mk + sdvprev * scv.y;                                      \
        float sdv = sur * (myv - kp);                                          \
        float y = Mqa + sdvprev * scv.z + sdv * scv.w;                         \
        by[(size_t)tcur * DS_ + c] = y;                                        \
        sdvprev = sdv;                                                         \
    }

    for (int t = 0; t < S_; t += 2) {
        REC_STEP(0, 1, t)
        REC_STEP(1, 0, t + 1)
    }
#undef REC_STEP
}

// =============================================================================
// Kernel 3: fused RMSNorm(y) * norm_weight, then @ W_o^T. Packed FFMA2.
// =============================================================================
__global__ __launch_bounds__(256) void out_kernel(
    const float* __restrict__ Wo, const float* __restrict__ nw,
    float* __restrict__ out)
{
    __shared__ __align__(16) float sY[128][68];   // [k][m]
    __shared__ __align__(16) float sW[16][132];   // [k][n]
    __shared__ float sScale[64];
    __shared__ float snw[128];

    const int tid = threadIdx.x;
    const int tx = tid & 31, ty = tid >> 5;
    const int m0 = blockIdx.x * 64, n0 = blockIdx.y * 128;

    if (tid < 128) snw[tid] = nw[tid];

#pragma unroll
    for (int it = 0; it < 8; it++) {
        int idx = tid + it * 256;
        int row = idx >> 5;
        int k4  = (idx & 31) * 4;
        float4 v = *(const float4*)&g_y[(size_t)(m0 + row) * DS_ + k4];
        sY[k4 + 0][row] = v.x; sY[k4 + 1][row] = v.y;
        sY[k4 + 2][row] = v.z; sY[k4 + 3][row] = v.w;
    }
    __syncthreads();

    {
        int row = tid >> 2, part = tid & 3;
        float ss = 0.f;
#pragma unroll
        for (int kkk = 0; kkk < 32; kkk++) {
            float v = sY[part * 32 + kkk][row];
            ss = fmaf(v, v, ss);
        }
        ss += __shfl_xor_sync(0xffffffffu, ss, 1);
        ss += __shfl_xor_sync(0xffffffffu, ss, 2);
        if (part == 0) sScale[row] = rsqrtf(ss * (1.f / 128.f) + 1e-6f);
    }
    __syncthreads();

    for (int idx = tid; idx < 128 * 64; idx += 256) {
        int k = idx >> 6, m = idx & 63;
        sY[k][m] *= sScale[m];
    }

    u64 acc2[8][2];
#pragma unroll
    for (int i = 0; i < 8; i++) { acc2[i][0] = 0ULL; acc2[i][1] = 0ULL; }

    for (int kc = 0; kc < DS_; kc += 16) {
        int n0a = tid >> 2, k0a = (tid & 3) * 4;
        float4 w0 = *(const float4*)&Wo[(size_t)(n0 + n0a) * DS_ + kc + k0a];
        int idx2 = tid + 256;
        int n0b = idx2 >> 2, k0b = (idx2 & 3) * 4;
        float4 w1 = *(const float4*)&Wo[(size_t)(n0 + n0b) * DS_ + kc + k0b];

        __syncthreads();
        sW[k0a + 0][n0a] = w0.x * snw[kc + k0a + 0];
        sW[k0a + 1][n0a] = w0.y * snw[kc + k0a + 1];
        sW[k0a + 2][n0a] = w0.z * snw[kc + k0a + 2];
        sW[k0a + 3][n0a] = w0.w * snw[kc + k0a + 3];
        sW[k0b + 0][n0b] = w1.x * snw[kc + k0b + 0];
        sW[k0b + 1][n0b] = w1.y * snw[kc + k0b + 1];
        sW[k0b + 2][n0b] = w1.z * snw[kc + k0b + 2];
        sW[k0b + 3][n0b] = w1.w * snw[kc + k0b + 3];
        __syncthreads();

#pragma unroll
        for (int k = 0; k < 16; k++) {
            ulonglong2 b4 = *(const ulonglong2*)&sW[k][tx * 4];
            float a_[8];
#pragma unroll
            for (int i = 0; i < 8; i++) a_[i] = sY[kc + k][ty * 8 + i];
#pragma unroll
            for (int i = 0; i < 8; i++) {
                u64 a2 = pk2(a_[i], a_[i]);
                acc2[i][0] = ffma2(a2, b4.x, acc2[i][0]);
                acc2[i][1] = ffma2(a2, b4.y, acc2[i][1]);
            }
        }
    }

#pragma unroll
    for (int i = 0; i < 8; i++) {
        float2 lo = up2(acc2[i][0]);
        float2 hi = up2(acc2[i][1]);
        float4 o = make_float4(lo.x, lo.y, hi.x, hi.y);
        *(float4*)&out[(size_t)(m0 + ty * 8 + i) * D_ + n0 + tx * 4] = o;
    }
}

// =============================================================================
extern "C" void kernel_launch(void* const* d_in, const int* in_sizes, int n_in,
                              void* d_out, int out_size)
{
    const float* x   = (const float*)d_in[0];
    const float* Wk  = (const float*)d_in[1];
    const float* Wv  = (const float*)d_in[2];
    const float* Wq  = (const float*)d_in[3];
    const float* Waw = (const float*)d_in[4];
    const float* Wab = (const float*)d_in[5];
    const float* lam = (const float*)d_in[6];
    const float* Wo  = (const float*)d_in[7];
    const float* nw  = (const float*)d_in[8];
    float* out = (float*)d_out;

    dim3 g1(MROWS / 64, 4);
    proj_kernel<<<g1, 256>>>(x, Wk, Wv, Wq, Waw, Wab, lam);

    derive_kernel<<<MROWS / 8, 256>>>();

    recurrence_kernel<<<B_, 128>>>();

    dim3 g3(MROWS / 64, D_ / 128);
    out_kernel<<<g3, 256>>>(Wo, nw, out);
}

// round 16
// speedup vs baseline: 1.8552x; 1.2028x over previous
#include <cuda_runtime.h>
#include <cstdint>

#define B_ 8
#define S_ 2048
#define D_ 1024
#define DS_ 128
#define MROWS (B_*S_)   // 16384

// ---------------- scratch (static device globals; no allocation) -------------
__device__ float g_k[MROWS*DS_];
__device__ float g_v[MROWS*DS_];
__device__ float g_q[MROWS*DS_];
__device__ float g_a[MROWS*DS_];
__device__ float g_w[MROWS*DS_];    // w_t  = a_t * c0_{t-1}
__device__ float g_aq[MROWS*DS_];   // aq_t = a_t * q_t
__device__ float4 g_scal[MROWS];    // (P1, K1, E1, E0) per (b,t)
__device__ float g_y[MROWS*DS_];

// ---------------- packed fp32x2 helpers (FFMA2 path) -------------------------
typedef unsigned long long u64;

__device__ __forceinline__ u64 pk2(float lo, float hi) {
    u64 r; asm("mov.b64 %0,{%1,%2};" : "=l"(r) : "f"(lo), "f"(hi)); return r;
}
__device__ __forceinline__ float2 up2(u64 v) {
    float2 r; asm("mov.b64 {%0,%1}, %2;" : "=f"(r.x), "=f"(r.y) : "l"(v)); return r;
}
__device__ __forceinline__ u64 ffma2(u64 a, u64 b, u64 c) {
    u64 d; asm("fma.rn.f32x2 %0,%1,%2,%3;" : "=l"(d) : "l"(a), "l"(b), "l"(c)); return d;
}
__device__ __forceinline__ u64 fmul2(u64 a, u64 b) {
    u64 d; asm("mul.rn.f32x2 %0,%1,%2;" : "=l"(d) : "l"(a), "l"(b)); return d;
}
__device__ __forceinline__ u64 fadd2(u64 a, u64 b) {
    u64 d; asm("add.rn.f32x2 %0,%1,%2;" : "=l"(d) : "l"(a), "l"(b)); return d;
}

// =============================================================================
// Kernel 1: input projections. O = X @ W^T with per-variant epilogue.
// Row-pair packed accumulators: thread tile = 4 row-pairs x 4 cols.
// A operand = LDS.64 broadcast of a row pair (no pk2); only 4 B pk2 per k.
// =============================================================================
__global__ __launch_bounds__(256) void proj_kernel(
    const float* __restrict__ x,
    const float* __restrict__ Wk, const float* __restrict__ Wv,
    const float* __restrict__ Wq, const float* __restrict__ Waw,
    const float* __restrict__ Wab, const float* __restrict__ lam)
{
    const int which = blockIdx.y;
    const float* W; float* O; int epi;
    if (which == 0)      { W = Wk;  O = g_k; epi = 1; }
    else if (which == 1) { W = Wq;  O = g_q; epi = 1; }
    else if (which == 2) { W = Wv;  O = g_v; epi = 0; }
    else                 { W = Waw; O = g_a; epi = 2; }

    __shared__ __align__(16) float sX[16][72];    // pad 72 -> row pairs 8B aligned
    __shared__ __align__(16) float sW[16][132];

    const int tid = threadIdx.x;
    const int tx  = tid & 31;   // 32 col-groups
    const int ty  = tid >> 5;   // 8 row-groups
    const int m0  = blockIdx.x * 64;

    // acc2[ip][jc] = packed (row 2ip, row 2ip+1) for col jc
    u64 acc2[4][4];
#pragma unroll
    for (int ip = 0; ip < 4; ip++)
#pragma unroll
        for (int jc = 0; jc < 4; jc++) acc2[ip][jc] = 0ULL;

    const int lxr = tid >> 2;
    const int lxk = (tid & 3) * 4;

    for (int kc = 0; kc < D_; kc += 16) {
        float4 xv = *(const float4*)&x[(size_t)(m0 + lxr) * D_ + kc + lxk];
        int n0a = tid >> 2, k0a = (tid & 3) * 4;
        float4 wv0 = *(const float4*)&W[(size_t)n0a * D_ + kc + k0a];
        int idx2 = tid + 256;
        int n0b = idx2 >> 2, k0b = (idx2 & 3) * 4;
        float4 wv1 = *(const float4*)&W[(size_t)n0b * D_ + kc + k0b];

        __syncthreads();
        sX[lxk + 0][lxr] = xv.x; sX[lxk + 1][lxr] = xv.y;
        sX[lxk + 2][lxr] = xv.z; sX[lxk + 3][lxr] = xv.w;
        sW[k0a + 0][n0a] = wv0.x; sW[k0a + 1][n0a] = wv0.y;
        sW[k0a + 2][n0a] = wv0.z; sW[k0a + 3][n0a] = wv0.w;
        sW[k0b + 0][n0b] = wv1.x; sW[k0b + 1][n0b] = wv1.y;
        sW[k0b + 2][n0b] = wv1.z; sW[k0b + 3][n0b] = wv1.w;
        __syncthreads();

#pragma unroll
        for (int k = 0; k < 16; k++) {
            float4 b4 = *(const float4*)&sW[k][tx * 4];
            u64 bb0 = pk2(b4.x, b4.x);
            u64 bb1 = pk2(b4.y, b4.y);
            u64 bb2 = pk2(b4.z, b4.z);
            u64 bb3 = pk2(b4.w, b4.w);
            const u64* ap = (const u64*)&sX[k][ty * 8];   // 4 row-pair broadcasts
#pragma unroll
            for (int ip = 0; ip < 4; ip++) {
                u64 a2 = ap[ip];
                acc2[ip][0] = ffma2(a2, bb0, acc2[ip][0]);
                acc2[ip][1] = ffma2(a2, bb1, acc2[ip][1]);
                acc2[ip][2] = ffma2(a2, bb2, acc2[ip][2]);
                acc2[ip][3] = ffma2(a2, bb3, acc2[ip][3]);
            }
        }
    }

    const int nbase = tx * 4;
    if (epi == 0) {
#pragma unroll
        for (int ip = 0; ip < 4; ip++) {
            float2 c0 = up2(acc2[ip][0]), c1 = up2(acc2[ip][1]);
            float2 c2 = up2(acc2[ip][2]), c3 = up2(acc2[ip][3]);
            int r = m0 + ty * 8 + 2 * ip;
            *(float4*)&O[(size_t)r * DS_ + nbase]       = make_float4(c0.x, c1.x, c2.x, c3.x);
            *(float4*)&O[(size_t)(r + 1) * DS_ + nbase] = make_float4(c0.y, c1.y, c2.y, c3.y);
        }
    } else if (epi == 1) {
#pragma unroll
        for (int ip = 0; ip < 4; ip++) {
            u64 ss2 = 0ULL;
#pragma unroll
            for (int jc = 0; jc < 4; jc++)
                ss2 = ffma2(acc2[ip][jc], acc2[ip][jc], ss2);
#pragma unroll
            for (int off = 16; off; off >>= 1) {
                u64 o = __shfl_xor_sync(0xffffffffu, ss2, off);
                ss2 = fadd2(ss2, o);
            }
            float2 ss = up2(ss2);
            float invx = 1.f / fmaxf(sqrtf(ss.x), 1e-12f);
            float invy = 1.f / fmaxf(sqrtf(ss.y), 1e-12f);
            float2 c0 = up2(acc2[ip][0]), c1 = up2(acc2[ip][1]);
            float2 c2 = up2(acc2[ip][2]), c3 = up2(acc2[ip][3]);
            int r = m0 + ty * 8 + 2 * ip;
            *(float4*)&O[(size_t)r * DS_ + nbase] =
                make_float4(c0.x * invx, c1.x * invx, c2.x * invx, c3.x * invx);
            *(float4*)&O[(size_t)(r + 1) * DS_ + nbase] =
                make_float4(c0.y * invy, c1.y * invy, c2.y * invy, c3.y * invy);
        }
    } else {
        float bias[4], loga[4];
#pragma unroll
        for (int j = 0; j < 4; j++) {
            int n = nbase + j;
            bias[j] = Wab[n];
            float sl = 1.f / (1.f + __expf(-lam[n]));
            loga[j] = __logf(sl + 1e-8f);
        }
#pragma unroll
        for (int ip = 0; ip < 4; ip++) {
            float2 c[4];
            c[0] = up2(acc2[ip][0]); c[1] = up2(acc2[ip][1]);
            c[2] = up2(acc2[ip][2]); c[3] = up2(acc2[ip][3]);
            float4 olo, ohi;
            float* plo = &olo.x; float* phi = &ohi.x;
#pragma unroll
            for (int j = 0; j < 4; j++) {
                float rlo = 1.f / (1.f + __expf(-(c[j].x + bias[j])));
                float rhi = 1.f / (1.f + __expf(-(c[j].y + bias[j])));
                plo[j] = __expf(8.f * rlo * loga[j]);
                phi[j] = __expf(8.f * rhi * loga[j]);
            }
            int r = m0 + ty * 8 + 2 * ip;
            *(float4*)&O[(size_t)r * DS_ + nbase]       = olo;
            *(float4*)&O[(size_t)(r + 1) * DS_ + nbase] = ohi;
        }
    }
}

// =============================================================================
// Kernel 1b: derive per-step vectors and scalars (parallel over (b,t)).
// =============================================================================
__global__ __launch_bounds__(256) void derive_kernel()
{
    const int m = (blockIdx.x * 256 + threadIdx.x) >> 5;   // global row
    const int lane = threadIdx.x & 31;
    if (m >= MROWS) return;
    const int t = m & (S_ - 1);
    const size_t ro = (size_t)m * DS_ + lane * 4;

    float4 qt = *(const float4*)&g_q[ro];
    float4 kt = *(const float4*)&g_k[ro];
    float4 at = *(const float4*)&g_a[ro];
    float4 kp = make_float4(0.f, 0.f, 0.f, 0.f);
    float4 ap = make_float4(1.f, 1.f, 1.f, 1.f);   // (1-ap)=0 -> c0p = 0 at t=0
    if (t > 0) {
        kp = *(const float4*)&g_k[ro - DS_];
        ap = *(const float4*)&g_a[ro - DS_];
    }

    float4 c0p, w, aq, c0c;
    c0p.x = (1.f - ap.x) * kp.x; c0p.y = (1.f - ap.y) * kp.y;
    c0p.z = (1.f - ap.z) * kp.z; c0p.w = (1.f - ap.w) * kp.w;
    w.x = at.x * c0p.x; w.y = at.y * c0p.y; w.z = at.z * c0p.z; w.w = at.w * c0p.w;
    aq.x = at.x * qt.x; aq.y = at.y * qt.y; aq.z = at.z * qt.z; aq.w = at.w * qt.w;
    c0c.x = (1.f - at.x) * kt.x; c0c.y = (1.f - at.y) * kt.y;
    c0c.z = (1.f - at.z) * kt.z; c0c.w = (1.f - at.w) * kt.w;

    float P1 = qt.x * c0p.x + qt.y * c0p.y + qt.z * c0p.z + qt.w * c0p.w;
    float K1 = kt.x * c0p.x + kt.y * c0p.y + kt.z * c0p.z + kt.w * c0p.w;
    float E1 = qt.x * w.x + qt.y * w.y + qt.z * w.z + qt.w * w.w;
    float E0 = qt.x * c0c.x + qt.y * c0c.y + qt.z * c0c.z + qt.w * c0c.w;
#pragma unroll
    for (int off = 16; off; off >>= 1) {
        P1 += __shfl_xor_sync(0xffffffffu, P1, off);
        K1 += __shfl_xor_sync(0xffffffffu, K1, off);
        E1 += __shfl_xor_sync(0xffffffffu, E1, off);
        E0 += __shfl_xor_sync(0xffffffffu, E0, off);
    }

    *(float4*)&g_w[ro]  = w;
    *(float4*)&g_aq[ro] = aq;
    if (lane == 0) g_scal[m] = make_float4(P1, K1, E1, E0);
}

// =============================================================================
// Kernel 2: recurrence, deferred rank-1. EXACT R12 version (measured best).
// 128 threads/CTA, 1 CTA per batch; thread c owns column g[:,c] as 64 packed
// fp32-pairs. One barrier per step.
// =============================================================================
__global__ __launch_bounds__(128, 1) void recurrence_kernel()
{
    const int b    = blockIdx.x;
    const int c    = threadIdx.x;
    const int warp = c >> 5;
    const int lane = c & 31;

    __shared__ __align__(16) float sq[2][DS_];
    __shared__ __align__(16) float sk[2][DS_];
    __shared__ __align__(16) float saq[2][DS_];
    __shared__ __align__(16) float sa[2][DS_];
    __shared__ __align__(16) float sw[2][DS_];
    __shared__ __align__(16) float sv2[2][DS_];
    __shared__ float4 ssc[2];
    __shared__ float red[2][4];

    u64 g[64];
#pragma unroll
    for (int j = 0; j < 64; j++) g[j] = 0ULL;

    const size_t base = (size_t)b * S_ * DS_;
    const float* bq  = g_q  + base;
    const float* bk  = g_k  + base;
    const float* baq = g_aq + base;
    const float* ba  = g_a  + base;
    const float* bw  = g_w  + base;
    const float* bv  = g_v  + base;
    const float4* bs = g_scal + (size_t)b * S_;
    float* by = g_y + base;

    // preload step 0
    sq[0][c] = bq[c];  sk[0][c] = bk[c]; saq[0][c] = baq[c];
    sa[0][c] = ba[c];  sw[0][c] = bw[c]; sv2[0][c] = bv[c];
    if (c == 0) ssc[0] = bs[0];
    __syncthreads();

    float sdvprev = 0.f;
    for (int t = 0; t < S_; ++t) {
        const int buf = t & 1;
        const int nb  = buf ^ 1;

        // global prefetch of step t+1 (latency hidden under the loops)
        float f0 = 0.f, f1 = 0.f, f2 = 0.f, f3 = 0.f, f4 = 0.f, f5 = 0.f;
        float4 sc4 = make_float4(0.f, 0.f, 0.f, 0.f);
        if (t + 1 < S_) {
            size_t o = (size_t)(t + 1) * DS_ + c;
            f0 = bq[o]; f1 = bk[o]; f2 = baq[o];
            f3 = ba[o]; f4 = bw[o]; f5 = bv[o];
            if (c == 0) sc4 = bs[t + 1];
        }

        // ---- loop A: three matvecs vs g (broadcast LDS, 6 acc chains) -------
        const ulonglong2* Q = (const ulonglong2*)&sq[buf][0];
        const ulonglong2* K = (const ulonglong2*)&sk[buf][0];
        const ulonglong2* AQ = (const ulonglong2*)&saq[buf][0];
        u64 mq0 = 0, mq1 = 0, mk0 = 0, mk1 = 0, ma0 = 0, ma1 = 0;
#pragma unroll
        for (int j = 0; j < 32; j++) {
            ulonglong2 q2 = Q[j];
            ulonglong2 k2 = K[j];
            ulonglong2 a2 = AQ[j];
            mq0 = ffma2(q2.x, g[2 * j],     mq0);
            mk0 = ffma2(k2.x, g[2 * j],     mk0);
            ma0 = ffma2(a2.x, g[2 * j],     ma0);
            mq1 = ffma2(q2.y, g[2 * j + 1], mq1);
            mk1 = ffma2(k2.y, g[2 * j + 1], mk1);
            ma1 = ffma2(a2.y, g[2 * j + 1], ma1);
        }
        float2 t1 = up2(fadd2(mq0, mq1));
        float Mq = t1.x + t1.y;
        float2 t2 = up2(fadd2(mk0, mk1));
        float Mk = t2.x + t2.y;
        float2 t3 = up2(fadd2(ma0, ma1));
        float Mqa = t3.x + t3.y;

        // pre-barrier scalar reads (broadcast / per-thread)
        float4 scv = ssc[buf];            // P1, K1, E1, E0
        float myv  = sv2[buf][c];

        float pred = Mq + sdvprev * scv.x;
        float d = myv - pred;
        float e = d * d;
        // shfl tree (interleaves with loop B below via scheduler)
#pragma unroll
        for (int off = 16; off; off >>= 1)
            e += __shfl_xor_sync(0xffffffffu, e, off);
        if (lane == 0) red[buf][warp] = e;

        // ---- loop B: g = a*g + sdvprev*w (independent of sur_t) -------------
        const ulonglong2* A = (const ulonglong2*)&sa[buf][0];
        const ulonglong2* Wv2 = (const ulonglong2*)&sw[buf][0];
        u64 sp2 = pk2(sdvprev, sdvprev);
#pragma unroll
        for (int j = 0; j < 32; j++) {
            ulonglong2 a2 = A[j];
            ulonglong2 w2 = Wv2[j];
            g[2 * j]     = ffma2(a2.x, g[2 * j],     fmul2(w2.x, sp2));
            g[2 * j + 1] = ffma2(a2.y, g[2 * j + 1], fmul2(w2.y, sp2));
        }

        // stash prefetched step t+1
        if (t + 1 < S_) {
            sq[nb][c] = f0;  sk[nb][c] = f1; saq[nb][c] = f2;
            sa[nb][c] = f3;  sw[nb][c] = f4; sv2[nb][c] = f5;
            if (c == 0) ssc[nb] = sc4;
        }
        __syncthreads();   // the ONLY barrier per step

        // ---- cheap sur-dependent tail ---------------------------------------
        float err = (red[buf][0] + red[buf][1]) + (red[buf][2] + red[buf][3]);
        float sur = 1.f / (1.f + __expf(-err * (1.f / 1.000001f)));
        float kp  = Mk + sdvprev * scv.y;
        float sdv = sur * (myv - kp);
        float y = Mqa + sdvprev * scv.z + sdv * scv.w;
        by[(size_t)t * DS_ + c] = y;
        sdvprev = sdv;
    }
}

// =============================================================================
// Kernel 3: fused RMSNorm(y) * norm_weight, then @ W_o^T. Packed FFMA2.
// =============================================================================
__global__ __launch_bounds__(256) void out_kernel(
    const float* __restrict__ Wo, const float* __restrict__ nw,
    float* __restrict__ out)
{
    __shared__ __align__(16) float sY[128][68];   // [k][m]
    __shared__ __align__(16) float sW[16][132];   // [k][n]
    __shared__ float sScale[64];
    __shared__ float snw[128];

    const int tid = threadIdx.x;
    const int tx = tid & 31, ty = tid >> 5;
    const int m0 = blockIdx.x * 64, n0 = blockIdx.y * 128;

    if (tid < 128) snw[tid] = nw[tid];

#pragma unroll
    for (int it = 0; it < 8; it++) {
        int idx = tid + it * 256;
        int row = idx >> 5;
        int k4  = (idx & 31) * 4;
        float4 v = *(const float4*)&g_y[(size_t)(m0 + row) * DS_ + k4];
        sY[k4 + 0][row] = v.x; sY[k4 + 1][row] = v.y;
        sY[k4 + 2][row] = v.z; sY[k4 + 3][row] = v.w;
    }
    __syncthreads();

    {
        int row = tid >> 2, part = tid & 3;
        float ss = 0.f;
#pragma unroll
        for (int kkk = 0; kkk < 32; kkk++) {
            float v = sY[part * 32 + kkk][row];
            ss = fmaf(v, v, ss);
        }
        ss += __shfl_xor_sync(0xffffffffu, ss, 1);
        ss += __shfl_xor_sync(0xffffffffu, ss, 2);
        if (part == 0) sScale[row] = rsqrtf(ss * (1.f / 128.f) + 1e-6f);
    }
    __syncthreads();

    for (int idx = tid; idx < 128 * 64; idx += 256) {
        int k = idx >> 6, m = idx & 63;
        sY[k][m] *= sScale[m];
    }

    u64 acc2[8][2];
#pragma unroll
    for (int i = 0; i < 8; i++) { acc2[i][0] = 0ULL; acc2[i][1] = 0ULL; }

    for (int kc = 0; kc < DS_; kc += 16) {
        int n0a = tid >> 2, k0a = (tid & 3) * 4;
        float4 w0 = *(const float4*)&Wo[(size_t)(n0 + n0a) * DS_ + kc + k0a];
        int idx2 = tid + 256;
        int n0b = idx2 >> 2, k0b = (idx2 & 3) * 4;
        float4 w1 = *(const float4*)&Wo[(size_t)(n0 + n0b) * DS_ + kc + k0b];

        __syncthreads();
        sW[k0a + 0][n0a] = w0.x * snw[kc + k0a + 0];
        sW[k0a + 1][n0a] = w0.y * snw[kc + k0a + 1];
        sW[k0a + 2][n0a] = w0.z * snw[kc + k0a + 2];
        sW[k0a + 3][n0a] = w0.w * snw[kc + k0a + 3];
        sW[k0b + 0][n0b] = w1.x * snw[kc + k0b + 0];
        sW[k0b + 1][n0b] = w1.y * snw[kc + k0b + 1];
        sW[k0b + 2][n0b] = w1.z * snw[kc + k0b + 2];
        sW[k0b + 3][n0b] = w1.w * snw[kc + k0b + 3];
        __syncthreads();

#pragma unroll
        for (int k = 0; k < 16; k++) {
            ulonglong2 b4 = *(const ulonglong2*)&sW[k][tx * 4];
            float a_[8];
#pragma unroll
            for (int i = 0; i < 8; i++) a_[i] = sY[kc + k][ty * 8 + i];
#pragma unroll
            for (int i = 0; i < 8; i++) {
                u64 a2 = pk2(a_[i], a_[i]);
                acc2[i][0] = ffma2(a2, b4.x, acc2[i][0]);
                acc2[i][1] = ffma2(a2, b4.y, acc2[i][1]);
            }
        }
    }

#pragma unroll
    for (int i = 0; i < 8; i++) {
        float2 lo = up2(acc2[i][0]);
        float2 hi = up2(acc2[i][1]);
        float4 o = make_float4(lo.x, lo.y, hi.x, hi.y);
        *(float4*)&out[(size_t)(m0 + ty * 8 + i) * D_ + n0 + tx * 4] = o;
    }
}

// =============================================================================
extern "C" void kernel_launch(void* const* d_in, const int* in_sizes, int n_in,
                              void* d_out, int out_size)
{
    const float* x   = (const float*)d_in[0];
    const float* Wk  = (const float*)d_in[1];
    const float* Wv  = (const float*)d_in[2];
    const float* Wq  = (const float*)d_in[3];
    const float* Waw = (const float*)d_in[4];
    const float* Wab = (const float*)d_in[5];
    const float* lam = (const float*)d_in[6];
    const float* Wo  = (const float*)d_in[7];
    const float* nw  = (const float*)d_in[8];
    float* out = (float*)d_out;

    dim3 g1(MROWS / 64, 4);
    proj_kernel<<<g1, 256>>>(x, Wk, Wv, Wq, Waw, Wab, lam);

    derive_kernel<<<MROWS / 8, 256>>>();

    recurrence_kernel<<<B_, 128>>>();

    dim3 g3(MROWS / 64, D_ / 128);
    out_kernel<<<g3, 256>>>(Wo, nw, out);
}